// round 1
// baseline (speedup 1.0000x reference)
#include <cuda_runtime.h>
#include <cstdint>

#define D_      128
#define NVARS   50000
#define V2_     100000
#define NCL     200000
#define NTOTAL  300000
#define NROUNDS 16

__device__ float g_h[(size_t)NTOTAL * D_];
__device__ float g_c[(size_t)NTOTAL * D_];
__device__ float g_msg[(size_t)NCL * D_];
__device__ float g_t0[(size_t)NCL * D_];
__device__ float g_t1[(size_t)NCL * D_];
__device__ float g_gates[(size_t)NCL * 4 * D_];

struct GemmArgs {
    const float *A0, *A1, *A2;
    const float *B0, *B1, *B2;
    int ldb0, ldb1, ldb2;
    int koff0, koff1, koff2;
    int nTerms;
    const float *bias0, *bias1;
    float *C;
    int M, N;
    int relu;
};

__global__ __launch_bounds__(256, 2) void gemm_kernel(GemmArgs a) {
    __shared__ float As[8][128];
    __shared__ float Bs[8][128];
    const int tid  = threadIdx.x;
    const int tr   = tid >> 4;
    const int tc   = tid & 15;
    const int brow = blockIdx.y << 7;
    const int bcol = blockIdx.x << 7;

    float acc[8][8];
#pragma unroll
    for (int i = 0; i < 8; ++i)
#pragma unroll
        for (int j = 0; j < 8; ++j) acc[i][j] = 0.f;

    const int a_row = tid >> 1;
    const int k4    = (tid & 1) << 2;

    const float* Aarr[3]  = {a.A0, a.A1, a.A2};
    const float* Barr[3]  = {a.B0, a.B1, a.B2};
    const int ldbarr[3]   = {a.ldb0, a.ldb1, a.ldb2};
    const int koffarr[3]  = {a.koff0, a.koff1, a.koff2};

    const int grow  = brow + a_row;
    const bool aval = grow < a.M;

    for (int t = 0; t < a.nTerms; ++t) {
        const float* Aptr = Aarr[t] + (size_t)grow * D_ + k4;
        const float* Bptr = Barr[t] + (size_t)(bcol + a_row) * ldbarr[t] + koffarr[t] + k4;
        for (int k0 = 0; k0 < 128; k0 += 8) {
            float4 av = aval ? *(const float4*)(Aptr + k0)
                             : make_float4(0.f, 0.f, 0.f, 0.f);
            float4 bv = *(const float4*)(Bptr + k0);
            __syncthreads();
            As[k4 + 0][a_row] = av.x; As[k4 + 1][a_row] = av.y;
            As[k4 + 2][a_row] = av.z; As[k4 + 3][a_row] = av.w;
            Bs[k4 + 0][a_row] = bv.x; Bs[k4 + 1][a_row] = bv.y;
            Bs[k4 + 2][a_row] = bv.z; Bs[k4 + 3][a_row] = bv.w;
            __syncthreads();
#pragma unroll
            for (int kk = 0; kk < 8; ++kk) {
                float4 a0 = *(const float4*)&As[kk][tr * 8];
                float4 a1 = *(const float4*)&As[kk][tr * 8 + 4];
                float4 b0 = *(const float4*)&Bs[kk][tc * 8];
                float4 b1 = *(const float4*)&Bs[kk][tc * 8 + 4];
                float af[8] = {a0.x, a0.y, a0.z, a0.w, a1.x, a1.y, a1.z, a1.w};
                float bf[8] = {b0.x, b0.y, b0.z, b0.w, b1.x, b1.y, b1.z, b1.w};
#pragma unroll
                for (int i = 0; i < 8; ++i)
#pragma unroll
                    for (int j = 0; j < 8; ++j)
                        acc[i][j] = fmaf(af[i], bf[j], acc[i][j]);
            }
        }
    }

    float bias[8];
#pragma unroll
    for (int j = 0; j < 8; ++j) {
        int col = bcol + tc * 8 + j;
        float b = a.bias0[col];
        if (a.bias1) b += a.bias1[col];
        bias[j] = b;
    }
#pragma unroll
    for (int i = 0; i < 8; ++i) {
        int row = brow + tr * 8 + i;
        if (row < a.M) {
            float v[8];
#pragma unroll
            for (int j = 0; j < 8; ++j) {
                float x = acc[i][j] + bias[j];
                v[j] = a.relu ? fmaxf(x, 0.f) : x;
            }
            float* cp = a.C + (size_t)row * a.N + bcol + tc * 8;
            *(float4*)cp       = make_float4(v[0], v[1], v[2], v[3]);
            *(float4*)(cp + 4) = make_float4(v[4], v[5], v[6], v[7]);
        }
    }
}

__global__ void scatter_kernel(const float* __restrict__ rows,
                               const int* __restrict__ gidx,
                               const int* __restrict__ sidx,
                               int E, float* __restrict__ out) {
    int e = blockIdx.x * 8 + threadIdx.y;
    if (e >= E) return;
    int s = gidx[e];
    int d = sidx[e];
    float4 v = *(const float4*)(rows + (size_t)s * D_ + threadIdx.x * 4);
    float* p = out + (size_t)d * D_ + threadIdx.x * 4;
    asm volatile("red.global.add.v4.f32 [%0], {%1, %2, %3, %4};"
                 :: "l"(p), "f"(v.x), "f"(v.y), "f"(v.z), "f"(v.w)
                 : "memory");
}

__device__ __forceinline__ float sigf(float x) { return 1.f / (1.f + expf(-x)); }

__global__ void lstm_kernel(const float* __restrict__ gates,
                            float* __restrict__ h, float* __restrict__ c, int M) {
    size_t idx = (size_t)blockIdx.x * blockDim.x + threadIdx.x;
    if (idx >= (size_t)M * 32) return;
    size_t r = idx >> 5;
    int q = (int)(idx & 31) * 4;
    const float* gb = gates + r * 512;
    float4 gi = *(const float4*)(gb + q);
    float4 gf = *(const float4*)(gb + 128 + q);
    float4 gg = *(const float4*)(gb + 256 + q);
    float4 go = *(const float4*)(gb + 384 + q);
    float4 cc = *(const float4*)(c + r * D_ + q);
    float4 c2, hh;
    c2.x = sigf(gf.x) * cc.x + sigf(gi.x) * tanhf(gg.x); hh.x = sigf(go.x) * tanhf(c2.x);
    c2.y = sigf(gf.y) * cc.y + sigf(gi.y) * tanhf(gg.y); hh.y = sigf(go.y) * tanhf(c2.y);
    c2.z = sigf(gf.z) * cc.z + sigf(gi.z) * tanhf(gg.z); hh.z = sigf(go.z) * tanhf(c2.z);
    c2.w = sigf(gf.w) * cc.w + sigf(gi.w) * tanhf(gg.w); hh.w = sigf(go.w) * tanhf(c2.w);
    *(float4*)(c + r * D_ + q) = c2;
    *(float4*)(h + r * D_ + q) = hh;
}

__global__ void init_kernel(const float* __restrict__ lw, const float* __restrict__ lb,
                            const float* __restrict__ cw, const float* __restrict__ cb,
                            float* __restrict__ h) {
    int d = threadIdx.x;
    size_t row = blockIdx.x;
    float v = (row < V2_) ? (lw[d] + lb[d]) : (cw[d] + cb[d]);
    h[row * D_ + d] = v;
}

__global__ void zero_kernel(float4* __restrict__ p, size_t n4) {
    size_t i = (size_t)blockIdx.x * blockDim.x + threadIdx.x;
    if (i < n4) p[i] = make_float4(0.f, 0.f, 0.f, 0.f);
}

__global__ void negcopy_kernel(const float* __restrict__ h, float* __restrict__ out) {
    size_t idx = (size_t)blockIdx.x * blockDim.x + threadIdx.x;
    if (idx >= (size_t)V2_ * 32) return;
    size_t r = idx >> 5;
    size_t lane = idx & 31;
    size_t sr = (r < NVARS) ? r + NVARS : r - NVARS;
    ((float4*)out)[r * 32 + lane] = ((const float4*)h)[sr * 32 + lane];
}

__global__ void copy_kernel(const float4* __restrict__ src, float4* __restrict__ dst, size_t n4) {
    size_t i = (size_t)blockIdx.x * blockDim.x + threadIdx.x;
    if (i < n4) dst[i] = src[i];
}

static void gemm1(const float* A, const float* B, const float* bias, int ldb,
                  float* C, int M, int N, int relu) {
    GemmArgs a = {};
    a.A0 = A; a.B0 = B; a.ldb0 = ldb; a.koff0 = 0; a.nTerms = 1;
    a.bias0 = bias; a.bias1 = nullptr; a.C = C; a.M = M; a.N = N; a.relu = relu;
    dim3 grid(N >> 7, (M + 127) >> 7);
    gemm_kernel<<<grid, 256>>>(a);
}

static void gemm2(const float* A0, const float* B0, int ldb0, int koff0,
                  const float* A1, const float* B1, int ldb1, int koff1,
                  const float* bias0, const float* bias1,
                  float* C, int M, int N) {
    GemmArgs a = {};
    a.A0 = A0; a.B0 = B0; a.ldb0 = ldb0; a.koff0 = koff0;
    a.A1 = A1; a.B1 = B1; a.ldb1 = ldb1; a.koff1 = koff1;
    a.nTerms = 2; a.bias0 = bias0; a.bias1 = bias1;
    a.C = C; a.M = M; a.N = N; a.relu = 0;
    dim3 grid(N >> 7, (M + 127) >> 7);
    gemm_kernel<<<grid, 256>>>(a);
}

static void gemm3(const float* A0, const float* B0, int ldb0, int koff0,
                  const float* A1, const float* B1, int ldb1, int koff1,
                  const float* A2, const float* B2, int ldb2, int koff2,
                  const float* bias0, const float* bias1,
                  float* C, int M, int N) {
    GemmArgs a = {};
    a.A0 = A0; a.B0 = B0; a.ldb0 = ldb0; a.koff0 = koff0;
    a.A1 = A1; a.B1 = B1; a.ldb1 = ldb1; a.koff1 = koff1;
    a.A2 = A2; a.B2 = B2; a.ldb2 = ldb2; a.koff2 = koff2;
    a.nTerms = 3; a.bias0 = bias0; a.bias1 = bias1;
    a.C = C; a.M = M; a.N = N; a.relu = 0;
    dim3 grid(N >> 7, (M + 127) >> 7);
    gemm_kernel<<<grid, 256>>>(a);
}

extern "C" void kernel_launch(void* const* d_in, const int* in_sizes, int n_in,
                              void* d_out, int out_size) {
    const float* L_init_w = (const float*)d_in[0];
    const float* L_init_b = (const float*)d_in[1];
    const float* C_init_w = (const float*)d_in[2];
    const float* C_init_b = (const float*)d_in[3];
    const float* Lmsg_w   = (const float*)d_in[4];
    const float* Lmsg_b   = (const float*)d_in[5];
    const float* Cmsg_w   = (const float*)d_in[6];
    const float* Cmsg_b   = (const float*)d_in[7];
    const float* Cu_wih   = (const float*)d_in[8];
    const float* Cu_whh   = (const float*)d_in[9];
    const float* Cu_bih   = (const float*)d_in[10];
    const float* Cu_bhh   = (const float*)d_in[11];
    const float* Lu_wih   = (const float*)d_in[12];
    const float* Lu_whh   = (const float*)d_in[13];
    const float* Lu_bih   = (const float*)d_in[14];
    const float* Lu_bhh   = (const float*)d_in[15];
    const int*   esrc     = (const int*)d_in[16];
    const int*   edst     = (const int*)d_in[17];
    const int E = in_sizes[16];

    float *h, *c, *msg, *t0, *t1, *gates;
    cudaGetSymbolAddress((void**)&h,     g_h);
    cudaGetSymbolAddress((void**)&c,     g_c);
    cudaGetSymbolAddress((void**)&msg,   g_msg);
    cudaGetSymbolAddress((void**)&t0,    g_t0);
    cudaGetSymbolAddress((void**)&t1,    g_t1);
    cudaGetSymbolAddress((void**)&gates, g_gates);

    init_kernel<<<NTOTAL, 128>>>(L_init_w, L_init_b, C_init_w, C_init_b, h);
    zero_kernel<<<((size_t)NTOTAL * 32 + 255) / 256, 256>>>((float4*)c, (size_t)NTOTAL * 32);

    dim3 sblk(32, 8);
    int sgrid = (E + 7) / 8;
    float* hC = h + (size_t)V2_ * D_;
    float* cC = c + (size_t)V2_ * D_;

    for (int r = 0; r < NROUNDS; ++r) {
        // literal -> clause messages: lm = MLP3(h_lit)
        gemm1(h,  Lmsg_w,                 Lmsg_b,            128, t0, V2_, 128, 1);
        gemm1(t0, Lmsg_w + 128 * 128,     Lmsg_b + 128,      128, t1, V2_, 128, 1);
        gemm1(t1, Lmsg_w + 2 * 128 * 128, Lmsg_b + 2 * 128,  128, t0, V2_, 128, 0);
        zero_kernel<<<((size_t)NCL * 32 + 255) / 256, 256>>>((float4*)msg, (size_t)NCL * 32);
        scatter_kernel<<<sgrid, sblk>>>(t0, esrc, edst, E, msg);

        // clause LSTM
        gemm2(msg, Cu_wih, 128, 0, hC, Cu_whh, 128, 0, Cu_bih, Cu_bhh, gates, NCL, 512);
        lstm_kernel<<<((size_t)NCL * 32 + 255) / 256, 256>>>(gates, hC, cC, NCL);

        // clause -> literal messages: cm = MLP3(h_clause)
        gemm1(hC, Cmsg_w,                 Cmsg_b,            128, t0, NCL, 128, 1);
        gemm1(t0, Cmsg_w + 128 * 128,     Cmsg_b + 128,      128, t1, NCL, 128, 1);
        gemm1(t1, Cmsg_w + 2 * 128 * 128, Cmsg_b + 2 * 128,  128, t0, NCL, 128, 0);
        zero_kernel<<<((size_t)V2_ * 32 + 255) / 256, 256>>>((float4*)msg, (size_t)V2_ * 32);
        scatter_kernel<<<sgrid, sblk>>>(t0, edst, esrc, E, msg);

        // literal LSTM: x = [l_msg, l_neg]
        negcopy_kernel<<<((size_t)V2_ * 32 + 255) / 256, 256>>>(h, t1);
        gemm3(msg, Lu_wih, 256, 0,
              t1,  Lu_wih, 256, 128,
              h,   Lu_whh, 128, 0,
              Lu_bih, Lu_bhh, gates, V2_, 512);
        lstm_kernel<<<((size_t)V2_ * 32 + 255) / 256, 256>>>(gates, h, c, V2_);
    }

    copy_kernel<<<((size_t)NTOTAL * 32 + 255) / 256, 256>>>(
        (const float4*)h, (float4*)d_out, (size_t)NTOTAL * 32);
}